// round 13
// baseline (speedup 1.0000x reference)
#include <cuda_runtime.h>
#include <math.h>

#define BATCH   4096
#define NBLK    66
#define XDIM    264      // 66 * 4
#define PHI_H   256
#define PHI_OUT 64
#define RHO_H   256
#define WARPS_PER_BLOCK 2
#define ROWS_PER_WARP   2
#define ROWS_PER_BLOCK  (WARPS_PER_BLOCK * ROWS_PER_WARP)   // 4
#define NBLOCKS (BATCH / ROWS_PER_BLOCK)                    // 1024

typedef unsigned long long ull;

// Global scratch: cross-batch max key + completion counter (self-resetting).
__device__ unsigned g_maxkey = 0u;
__device__ unsigned g_done   = 0u;

// ---- packed f32x2 helpers ----
__device__ __forceinline__ ull ffma2(ull a, ull b, ull c) {
    ull d; asm("fma.rn.f32x2 %0, %1, %2, %3;" : "=l"(d) : "l"(a), "l"(b), "l"(c)); return d;
}
__device__ __forceinline__ ull add2(ull a, ull b) {
    ull d; asm("add.rn.f32x2 %0, %1, %2;" : "=l"(d) : "l"(a), "l"(b)); return d;
}
__device__ __forceinline__ ull pack2(float lo, float hi) {
    ull v; asm("mov.b64 %0, {%1, %2};" : "=l"(v) : "f"(lo), "f"(hi)); return v;
}
__device__ __forceinline__ float2 unpack2(ull v) {
    float2 r; asm("mov.b64 {%0, %1}, %2;" : "=f"(r.x), "=f"(r.y) : "l"(v)); return r;
}
__device__ __forceinline__ ull dup2(float v) { return pack2(v, v); }

// Monotonic float->uint key.
__device__ __forceinline__ unsigned fkey(float f) {
    unsigned b = __float_as_uint(f);
    return (b & 0x80000000u) ? ~b : (b | 0x80000000u);
}
__device__ __forceinline__ float kinv(unsigned k) {
    unsigned b = (k & 0x80000000u) ? (k & 0x7fffffffu) : ~k;
    return __uint_as_float(b);
}

__global__ __launch_bounds__(32 * WARPS_PER_BLOCK, 8) void bn_main_kernel(
    const float* __restrict__ x,
    const float* __restrict__ pw1, const float* __restrict__ pb1,
    const float* __restrict__ pw2, const float* __restrict__ pb2,
    const float* __restrict__ rw1, const float* __restrict__ rb1,
    const float* __restrict__ rw2, const float* __restrict__ rb2,
    float* __restrict__ out)
{
    // All hot-loop operands staged PRE-DUPLICATED as (v,v) ull pairs:
    // packed FFMA2 operands come from single broadcast LDS.64 — zero MOVs.
    __shared__ __align__(16) ull xdup[WARPS_PER_BLOCK][ROWS_PER_WARP][NBLK][5]; // [4]+pad
    __shared__ __align__(16) ull Hs2[WARPS_PER_BLOCK][ROWS_PER_WARP][PHI_H];
    __shared__ __align__(16) ull Xs2[WARPS_PER_BLOCK][ROWS_PER_WARP][PHI_OUT];
    __shared__ unsigned s_max;
    __shared__ bool     s_last;

    const int tid  = threadIdx.x;
    const int w    = tid >> 5;
    const int lane = tid & 31;
    if (tid == 0) s_max = 0u;

    const int bA = blockIdx.x * ROWS_PER_BLOCK + w * ROWS_PER_WARP;  // row A
    const int bB = bA + 1;                                           // row B

    // ---- stage both x rows into shared, duplicated (coalesced LDG.128 reads) ----
    {
        const float4* rA = reinterpret_cast<const float4*>(x + (size_t)bA * XDIM);
        const float4* rB = reinterpret_cast<const float4*>(x + (size_t)bB * XDIM);
        for (int n = lane; n < NBLK; n += 32) {
            const float4 a = rA[n];
            const float4 b = rB[n];
            xdup[w][0][n][0] = dup2(a.x);  xdup[w][0][n][1] = dup2(a.y);
            xdup[w][0][n][2] = dup2(a.z);  xdup[w][0][n][3] = dup2(a.w);
            xdup[w][1][n][0] = dup2(b.x);  xdup[w][1][n][1] = dup2(b.y);
            xdup[w][1][n][2] = dup2(b.z);  xdup[w][1][n][3] = dup2(b.w);
        }
    }
    __syncwarp();

    // ---- preload layer-1 weights packed over unit pairs:
    //      pair k2 covers units (lane + 64*k2, lane + 64*k2 + 32) ----
    ull w1p[4][4], b1p[4];
    #pragma unroll
    for (int k2 = 0; k2 < 4; k2++) {
        const int ja = lane + 64 * k2;
        const int jb = ja + 32;
        b1p[k2] = pack2(__ldg(pb1 + ja), __ldg(pb1 + jb));
        #pragma unroll
        for (int r = 0; r < 4; r++)
            w1p[r][k2] = pack2(__ldg(pw1 + r * PHI_H + ja), __ldg(pw1 + r * PHI_H + jb));
    }

    // ---- layer 1 + block-sum, both rows interleaved; all operands LDS.64 ----
    ull HA[4], HB[4];
    #pragma unroll
    for (int k2 = 0; k2 < 4; k2++) { HA[k2] = 0ull; HB[k2] = 0ull; }

    #pragma unroll 2
    for (int n = 0; n < NBLK; n++) {
        const ull ax = xdup[w][0][n][0], ay = xdup[w][0][n][1];
        const ull az = xdup[w][0][n][2], aw = xdup[w][0][n][3];
        const ull bx = xdup[w][1][n][0], by = xdup[w][1][n][1];
        const ull bz = xdup[w][1][n][2], bw = xdup[w][1][n][3];
        #pragma unroll
        for (int k2 = 0; k2 < 4; k2++) {
            ull tA = ffma2(w1p[0][k2], ax, b1p[k2]);
            ull tB = ffma2(w1p[0][k2], bx, b1p[k2]);
            tA = ffma2(w1p[1][k2], ay, tA);
            tB = ffma2(w1p[1][k2], by, tB);
            tA = ffma2(w1p[2][k2], az, tA);
            tB = ffma2(w1p[2][k2], bz, tB);
            tA = ffma2(w1p[3][k2], aw, tA);
            tB = ffma2(w1p[3][k2], bw, tB);
            const float2 uA = unpack2(tA);
            const float2 uB = unpack2(tB);
            HA[k2] = add2(HA[k2], pack2(fmaxf(uA.x, 0.f), fmaxf(uA.y, 0.f)));
            HB[k2] = add2(HB[k2], pack2(fmaxf(uB.x, 0.f), fmaxf(uB.y, 0.f)));
        }
    }
    // store H duplicated (one-time dup cost)
    #pragma unroll
    for (int k2 = 0; k2 < 4; k2++) {
        const float2 uA = unpack2(HA[k2]);
        const float2 uB = unpack2(HB[k2]);
        Hs2[w][0][lane + 64 * k2]      = dup2(uA.x);
        Hs2[w][0][lane + 64 * k2 + 32] = dup2(uA.y);
        Hs2[w][1][lane + 64 * k2]      = dup2(uB.x);
        Hs2[w][1][lane + 64 * k2 + 32] = dup2(uB.y);
    }
    __syncwarp();

    // ---- X = H @ W2 + 66*b2 ; lane owns packed cols (2*lane, 2*lane+1);
    //      H via broadcast LDS.64 (pre-dup), weights via LDG.64, shared across rows ----
    {
        const int c0 = 2 * lane;
        const char* pw2c = reinterpret_cast<const char*>(pw2 + c0);
        ull accA0 = 0ull, accB0 = 0ull, accA1 = 0ull, accB1 = 0ull;
        #pragma unroll 8
        for (int j = 0; j < PHI_H; j += 4) {
            const ull hA0 = Hs2[w][0][j],     hA1 = Hs2[w][0][j + 1];
            const ull hA2 = Hs2[w][0][j + 2], hA3 = Hs2[w][0][j + 3];
            const ull hB0 = Hs2[w][1][j],     hB1 = Hs2[w][1][j + 1];
            const ull hB2 = Hs2[w][1][j + 2], hB3 = Hs2[w][1][j + 3];
            const size_t base = (size_t)j * (PHI_OUT * 4);
            const ull w0 = __ldg(reinterpret_cast<const ull*>(pw2c + base));
            const ull w1 = __ldg(reinterpret_cast<const ull*>(pw2c + base + PHI_OUT * 4));
            const ull w2 = __ldg(reinterpret_cast<const ull*>(pw2c + base + PHI_OUT * 8));
            const ull w3 = __ldg(reinterpret_cast<const ull*>(pw2c + base + PHI_OUT * 12));
            accA0 = ffma2(hA0, w0, accA0);
            accB0 = ffma2(hB0, w0, accB0);
            accA1 = ffma2(hA1, w1, accA1);
            accB1 = ffma2(hB1, w1, accB1);
            accA0 = ffma2(hA2, w2, accA0);
            accB0 = ffma2(hB2, w2, accB0);
            accA1 = ffma2(hA3, w3, accA1);
            accB1 = ffma2(hB3, w3, accB1);
        }
        const float2 bv = __ldg(reinterpret_cast<const float2*>(pb2 + c0));
        const ull b66 = pack2(66.f * bv.x, 66.f * bv.y);
        const float2 uA = unpack2(add2(add2(accA0, accA1), b66));
        const float2 uB = unpack2(add2(add2(accB0, accB1), b66));
        Xs2[w][0][c0]     = dup2(uA.x);
        Xs2[w][0][c0 + 1] = dup2(uA.y);
        Xs2[w][1][c0]     = dup2(uB.x);
        Xs2[w][1][c0 + 1] = dup2(uB.y);
    }
    __syncwarp();

    // ---- rho layer 1: lane owns 8 consecutive units (4 packed pairs);
    //      X via broadcast LDS.64 (pre-dup), weights shared across rows ----
    const int j0 = 8 * lane;
    ull tA[4], tB[4];
    {
        const ulonglong2 ra = __ldg(reinterpret_cast<const ulonglong2*>(rb1 + j0));
        const ulonglong2 rb = __ldg(reinterpret_cast<const ulonglong2*>(rb1 + j0 + 4));
        tA[0] = ra.x; tA[1] = ra.y; tA[2] = rb.x; tA[3] = rb.y;
        tB[0] = ra.x; tB[1] = ra.y; tB[2] = rb.x; tB[3] = rb.y;
    }
    #pragma unroll 4
    for (int i = 0; i < PHI_OUT; i += 4) {
        #pragma unroll
        for (int q = 0; q < 4; q++) {
            const ull xA = Xs2[w][0][i + q];
            const ull xB = Xs2[w][1][i + q];
            const ulonglong2 wa = __ldg(reinterpret_cast<const ulonglong2*>(rw1 + (i + q) * RHO_H + j0));
            const ulonglong2 wb = __ldg(reinterpret_cast<const ulonglong2*>(rw1 + (i + q) * RHO_H + j0 + 4));
            tA[0] = ffma2(xA, wa.x, tA[0]);  tB[0] = ffma2(xB, wa.x, tB[0]);
            tA[1] = ffma2(xA, wa.y, tA[1]);  tB[1] = ffma2(xB, wa.y, tB[1]);
            tA[2] = ffma2(xA, wb.x, tA[2]);  tB[2] = ffma2(xB, wb.x, tB[2]);
            tA[3] = ffma2(xA, wb.y, tA[3]);  tB[3] = ffma2(xB, wb.y, tB[3]);
        }
    }

    // ---- relu + rho layer 2 (rw2 rows j0..j0+7); loads shared; packed (a0,a1) ----
    ull aA2 = 0ull, aB2 = 0ull;
    {
        const ulonglong2 q01 = __ldg(reinterpret_cast<const ulonglong2*>(rw2 + 2 * j0));
        const ulonglong2 q23 = __ldg(reinterpret_cast<const ulonglong2*>(rw2 + 2 * j0 + 4));
        const ulonglong2 q45 = __ldg(reinterpret_cast<const ulonglong2*>(rw2 + 2 * j0 + 8));
        const ulonglong2 q67 = __ldg(reinterpret_cast<const ulonglong2*>(rw2 + 2 * j0 + 12));
        const float2 uA0 = unpack2(tA[0]), uA1 = unpack2(tA[1]);
        const float2 uA2 = unpack2(tA[2]), uA3 = unpack2(tA[3]);
        const float2 uB0 = unpack2(tB[0]), uB1 = unpack2(tB[1]);
        const float2 uB2 = unpack2(tB[2]), uB3 = unpack2(tB[3]);
        aA2 = ffma2(dup2(fmaxf(uA0.x, 0.f)), q01.x, aA2);
        aB2 = ffma2(dup2(fmaxf(uB0.x, 0.f)), q01.x, aB2);
        aA2 = ffma2(dup2(fmaxf(uA0.y, 0.f)), q01.y, aA2);
        aB2 = ffma2(dup2(fmaxf(uB0.y, 0.f)), q01.y, aB2);
        aA2 = ffma2(dup2(fmaxf(uA1.x, 0.f)), q23.x, aA2);
        aB2 = ffma2(dup2(fmaxf(uB1.x, 0.f)), q23.x, aB2);
        aA2 = ffma2(dup2(fmaxf(uA1.y, 0.f)), q23.y, aA2);
        aB2 = ffma2(dup2(fmaxf(uB1.y, 0.f)), q23.y, aB2);
        aA2 = ffma2(dup2(fmaxf(uA2.x, 0.f)), q45.x, aA2);
        aB2 = ffma2(dup2(fmaxf(uB2.x, 0.f)), q45.x, aB2);
        aA2 = ffma2(dup2(fmaxf(uA2.y, 0.f)), q45.y, aA2);
        aB2 = ffma2(dup2(fmaxf(uB2.y, 0.f)), q45.y, aB2);
        aA2 = ffma2(dup2(fmaxf(uA3.x, 0.f)), q67.x, aA2);
        aB2 = ffma2(dup2(fmaxf(uB3.x, 0.f)), q67.x, aB2);
        aA2 = ffma2(dup2(fmaxf(uA3.y, 0.f)), q67.y, aA2);
        aB2 = ffma2(dup2(fmaxf(uB3.y, 0.f)), q67.y, aB2);
    }

    // ---- barrier term over neighbors n = 2..65 (2 per lane per row) ----
    float bxA = 0.f, byA = 0.f, bxB = 0.f, byB = 0.f;
    #pragma unroll
    for (int q = 0; q < 2; q++) {
        const int n = 2 + lane + 32 * q;
        {
            const float px = *reinterpret_cast<const float*>(&xdup[w][0][n][0]);
            const float py = *reinterpret_cast<const float*>(&xdup[w][0][n][1]);
            const float dm = sqrtf(px * px + py * py) - 0.15f;
            const float inv = 1.f / (dm * dm);
            bxA -= px * inv;  byA -= py * inv;
        }
        {
            const float px = *reinterpret_cast<const float*>(&xdup[w][1][n][0]);
            const float py = *reinterpret_cast<const float*>(&xdup[w][1][n][1]);
            const float dm = sqrtf(px * px + py * py) - 0.15f;
            const float inv = 1.f / (dm * dm);
            bxB -= px * inv;  byB -= py * inv;
        }
    }

    // ---- warp butterfly reduce ----
    float a0A, a1A, a0B, a1B;
    { const float2 u = unpack2(aA2); a0A = u.x; a1A = u.y; }
    { const float2 u = unpack2(aB2); a0B = u.x; a1B = u.y; }
    #pragma unroll
    for (int off = 16; off > 0; off >>= 1) {
        a0A += __shfl_xor_sync(0xffffffff, a0A, off);
        a1A += __shfl_xor_sync(0xffffffff, a1A, off);
        a0B += __shfl_xor_sync(0xffffffff, a0B, off);
        a1B += __shfl_xor_sync(0xffffffff, a1B, off);
        bxA += __shfl_xor_sync(0xffffffff, bxA, off);
        byA += __shfl_xor_sync(0xffffffff, byA, off);
        bxB += __shfl_xor_sync(0xffffffff, bxB, off);
        byB += __shfl_xor_sync(0xffffffff, byB, off);
    }

    __syncthreads();  // orders s_max init before atomics below
    if (lane == 0) {
        const float rb20 = __ldg(rb2), rb21 = __ldg(rb2 + 1);
        const float rA0 = 2.0f * tanhf(a0A + rb20) + bxA;
        const float rA1 = 2.0f * tanhf(a1A + rb21) + byA;
        const float rB0 = 2.0f * tanhf(a0B + rb20) + bxB;
        const float rB1 = 2.0f * tanhf(a1B + rb21) + byB;
        out[2 * bA]     = rA0;
        out[2 * bA + 1] = rA1;
        out[2 * bB]     = rB0;
        out[2 * bB + 1] = rB1;
        const unsigned k = max(max(fkey(rA0), fkey(rA1)), max(fkey(rB0), fkey(rB1)));
        atomicMax(&s_max, k);
    }
    __syncthreads();

    // ---- block max -> global; last block applies global rescale ----
    if (tid == 0) {
        atomicMax(&g_maxkey, s_max);
        __threadfence();
        const unsigned prev = atomicAdd(&g_done, 1u);
        s_last = (prev == (unsigned)(gridDim.x - 1));
    }
    __syncthreads();

    if (s_last) {
        __threadfence();
        const float mx    = kinv(atomicAdd(&g_maxkey, 0u));
        const float scale = 2.0f / mx;
        if (scale < 1.0f) {
            float4* o4 = reinterpret_cast<float4*>(out);
            for (int i = tid; i < BATCH * 2 / 4; i += blockDim.x) {
                float4 v = o4[i];
                v.x *= scale; v.y *= scale; v.z *= scale; v.w *= scale;
                o4[i] = v;
            }
        }
        __syncthreads();
        if (tid == 0) {
            g_maxkey = 0u;
            __threadfence();
            atomicExch(&g_done, 0u);
        }
    }
}

extern "C" void kernel_launch(void* const* d_in, const int* in_sizes, int n_in,
                              void* d_out, int out_size)
{
    const float* x   = (const float*)d_in[0];
    const float* pw1 = (const float*)d_in[1];
    const float* pb1 = (const float*)d_in[2];
    const float* pw2 = (const float*)d_in[3];
    const float* pb2 = (const float*)d_in[4];
    const float* rw1 = (const float*)d_in[5];
    const float* rb1 = (const float*)d_in[6];
    const float* rw2 = (const float*)d_in[7];
    const float* rb2 = (const float*)d_in[8];
    float* out = (float*)d_out;

    bn_main_kernel<<<NBLOCKS, 32 * WARPS_PER_BLOCK>>>(
        x, pw1, pb1, pw2, pb2, rw1, rb1, rw2, rb2, out);
}

// round 14
// speedup vs baseline: 1.1568x; 1.1568x over previous
#include <cuda_runtime.h>
#include <math.h>

#define BATCH   4096
#define NBLK    66
#define XDIM    264      // 66 * 4
#define PHI_H   256
#define PHI_OUT 64
#define RHO_H   256
#define WARPS_PER_BLOCK 4
#define PAIRS           2
#define ROWS_PER_BLOCK  4                    // 2 rows per warp-pair
#define NBLOCKS (BATCH / ROWS_PER_BLOCK)     // 1024

typedef unsigned long long ull;

// Global scratch: cross-batch max key + completion counter (self-resetting).
__device__ unsigned g_maxkey = 0u;
__device__ unsigned g_done   = 0u;

// ---- packed f32x2 helpers ----
__device__ __forceinline__ ull ffma2(ull a, ull b, ull c) {
    ull d; asm("fma.rn.f32x2 %0, %1, %2, %3;" : "=l"(d) : "l"(a), "l"(b), "l"(c)); return d;
}
__device__ __forceinline__ ull add2(ull a, ull b) {
    ull d; asm("add.rn.f32x2 %0, %1, %2;" : "=l"(d) : "l"(a), "l"(b)); return d;
}
__device__ __forceinline__ ull pack2(float lo, float hi) {
    ull v; asm("mov.b64 %0, {%1, %2};" : "=l"(v) : "f"(lo), "f"(hi)); return v;
}
__device__ __forceinline__ float2 unpack2(ull v) {
    float2 r; asm("mov.b64 {%0, %1}, %2;" : "=f"(r.x), "=f"(r.y) : "l"(v)); return r;
}
__device__ __forceinline__ ull dup2(float v) { return pack2(v, v); }

// Monotonic float->uint key.
__device__ __forceinline__ unsigned fkey(float f) {
    unsigned b = __float_as_uint(f);
    return (b & 0x80000000u) ? ~b : (b | 0x80000000u);
}
__device__ __forceinline__ float kinv(unsigned k) {
    unsigned b = (k & 0x80000000u) ? (k & 0x7fffffffu) : ~k;
    return __uint_as_float(b);
}

__global__ __launch_bounds__(32 * WARPS_PER_BLOCK, 7) void bn_main_kernel(
    const float* __restrict__ x,
    const float* __restrict__ pw1, const float* __restrict__ pb1,
    const float* __restrict__ pw2, const float* __restrict__ pb2,
    const float* __restrict__ rw1, const float* __restrict__ rb1,
    const float* __restrict__ rw2, const float* __restrict__ rb2,
    float* __restrict__ out)
{
    // Per pair: 2 batch rows, processed by 2 cooperating warps (members 0/1).
    // Member m owns: layer-1 units [128m,128m+128), X-sum j in [128m,128m+128),
    // rho1 i in [32m, 32m+32). Partials exchanged via shared.
    __shared__ __align__(16) float xs[PAIRS][2][XDIM];
    // ubuf: time-multiplexed.  Phase 1 (layer-1 -> X): H as floats,
    //   Hsf[row*256 + j] (first 4KB of each pair's region).
    // Phase 2 (rho1 -> finish): rho partials, ubuf[p][member][row][lane*4+k] (ull).
    __shared__ __align__(16) ull   ubuf[PAIRS][2][2][128];
    __shared__ __align__(16) float Xp[PAIRS][2][2][PHI_OUT];  // [pair][member][row][col]
    __shared__ unsigned s_max;
    __shared__ bool     s_last;

    const int tid  = threadIdx.x;
    const int w    = tid >> 5;
    const int lane = tid & 31;
    const int p    = w >> 1;      // pair id
    const int m    = w & 1;       // member id
    if (tid == 0) s_max = 0u;

    const int bA   = blockIdx.x * ROWS_PER_BLOCK + p * 2;  // pair's first row
    const int brow = bA + m;                               // this warp's output row

    // ---- stage: member m stages row m of its pair (coalesced float4) ----
    {
        const float4* src = reinterpret_cast<const float4*>(x + (size_t)brow * XDIM);
        float4* dst = reinterpret_cast<float4*>(xs[p][m]);
        for (int n = lane; n < NBLK; n += 32) dst[n] = src[n];
    }
    __syncthreads();   // both rows staged; also orders s_max init

    // ---- layer-1 weights for member's half: units ja = 128m + lane + 64*k2 (+32) ----
    ull w1p[4][2], b1p[2];
    #pragma unroll
    for (int k2 = 0; k2 < 2; k2++) {
        const int ja = 128 * m + lane + 64 * k2;
        const int jb = ja + 32;
        b1p[k2] = pack2(__ldg(pb1 + ja), __ldg(pb1 + jb));
        #pragma unroll
        for (int r = 0; r < 4; r++)
            w1p[r][k2] = pack2(__ldg(pw1 + r * PHI_H + ja), __ldg(pw1 + r * PHI_H + jb));
    }

    float* Hsf = reinterpret_cast<float*>(&ubuf[p][0][0][0]);  // [row*256 + j]

    // ---- layer 1 + block-sum, both rows, member's 128 units ----
    {
        ull HA[2] = {0ull, 0ull}, HB[2] = {0ull, 0ull};
        const float4* sA4 = reinterpret_cast<const float4*>(xs[p][0]);
        const float4* sB4 = reinterpret_cast<const float4*>(xs[p][1]);
        #pragma unroll 2
        for (int n = 0; n < NBLK; n++) {
            const float4 sa = sA4[n];
            const float4 sb = sB4[n];
            const ull ax = dup2(sa.x), ay = dup2(sa.y), az = dup2(sa.z), aw = dup2(sa.w);
            const ull bx = dup2(sb.x), by = dup2(sb.y), bz = dup2(sb.z), bw = dup2(sb.w);
            #pragma unroll
            for (int k2 = 0; k2 < 2; k2++) {
                ull tA = ffma2(w1p[0][k2], ax, b1p[k2]);
                ull tB = ffma2(w1p[0][k2], bx, b1p[k2]);
                tA = ffma2(w1p[1][k2], ay, tA);
                tB = ffma2(w1p[1][k2], by, tB);
                tA = ffma2(w1p[2][k2], az, tA);
                tB = ffma2(w1p[2][k2], bz, tB);
                tA = ffma2(w1p[3][k2], aw, tA);
                tB = ffma2(w1p[3][k2], bw, tB);
                const float2 uA = unpack2(tA);
                const float2 uB = unpack2(tB);
                HA[k2] = add2(HA[k2], pack2(fmaxf(uA.x, 0.f), fmaxf(uA.y, 0.f)));
                HB[k2] = add2(HB[k2], pack2(fmaxf(uB.x, 0.f), fmaxf(uB.y, 0.f)));
            }
        }
        #pragma unroll
        for (int k2 = 0; k2 < 2; k2++) {
            const float2 uA = unpack2(HA[k2]);
            const float2 uB = unpack2(HB[k2]);
            const int j = 128 * m + lane + 64 * k2;
            Hsf[j]            = uA.x;
            Hsf[j + 32]       = uA.y;
            Hsf[256 + j]      = uB.x;
            Hsf[256 + j + 32] = uB.y;
        }
    }
    __syncwarp();   // member reads only its own H range -> warp sync suffices

    // ---- X partial: sum over member's j range; lane owns cols (2*lane, 2*lane+1) ----
    {
        const int c0 = 2 * lane;
        const char* pw2c = reinterpret_cast<const char*>(pw2 + c0);
        ull accA0 = 0ull, accA1 = 0ull, accB0 = 0ull, accB1 = 0ull;
        const int jbeg = 128 * m;
        #pragma unroll 8
        for (int jo = 0; jo < 128; jo += 4) {
            const int j = jbeg + jo;
            const float4 hA = *reinterpret_cast<const float4*>(&Hsf[j]);
            const float4 hB = *reinterpret_cast<const float4*>(&Hsf[256 + j]);
            const size_t base = (size_t)j * (PHI_OUT * 4);
            const ull w0 = __ldg(reinterpret_cast<const ull*>(pw2c + base));
            const ull w1 = __ldg(reinterpret_cast<const ull*>(pw2c + base + PHI_OUT * 4));
            const ull w2 = __ldg(reinterpret_cast<const ull*>(pw2c + base + PHI_OUT * 8));
            const ull w3 = __ldg(reinterpret_cast<const ull*>(pw2c + base + PHI_OUT * 12));
            accA0 = ffma2(dup2(hA.x), w0, accA0);
            accB0 = ffma2(dup2(hB.x), w0, accB0);
            accA1 = ffma2(dup2(hA.y), w1, accA1);
            accB1 = ffma2(dup2(hB.y), w1, accB1);
            accA0 = ffma2(dup2(hA.z), w2, accA0);
            accB0 = ffma2(dup2(hB.z), w2, accB0);
            accA1 = ffma2(dup2(hA.w), w3, accA1);
            accB1 = ffma2(dup2(hB.w), w3, accB1);
        }
        const float2 uA = unpack2(add2(accA0, accA1));
        const float2 uB = unpack2(add2(accB0, accB1));
        Xp[p][m][0][c0]     = uA.x;
        Xp[p][m][0][c0 + 1] = uA.y;
        Xp[p][m][1][c0]     = uB.x;
        Xp[p][m][1][c0 + 1] = uB.y;
    }
    __syncthreads();

    // ---- combine X for row m (overwrite member-0 slot in place) ----
    {
        const int c0 = 2 * lane;
        const float2 bv = __ldg(reinterpret_cast<const float2*>(pb2 + c0));
        const float xf0 = Xp[p][0][m][c0]     + Xp[p][1][m][c0]     + 66.f * bv.x;
        const float xf1 = Xp[p][0][m][c0 + 1] + Xp[p][1][m][c0 + 1] + 66.f * bv.y;
        Xp[p][0][m][c0]     = xf0;
        Xp[p][0][m][c0 + 1] = xf1;
    }
    __syncthreads();

    // ---- rho1 partial: member's i range [32m, 32m+32); lane owns 8 units j0..j0+7 ----
    const int j0 = 8 * lane;
    ull tA[4], tB[4];
    if (m == 0) {
        const ulonglong2 ra = __ldg(reinterpret_cast<const ulonglong2*>(rb1 + j0));
        const ulonglong2 rb = __ldg(reinterpret_cast<const ulonglong2*>(rb1 + j0 + 4));
        tA[0] = ra.x; tA[1] = ra.y; tA[2] = rb.x; tA[3] = rb.y;
        tB[0] = ra.x; tB[1] = ra.y; tB[2] = rb.x; tB[3] = rb.y;
    } else {
        tA[0] = tA[1] = tA[2] = tA[3] = 0ull;
        tB[0] = tB[1] = tB[2] = tB[3] = 0ull;
    }
    {
        const int ibeg = 32 * m;
        #pragma unroll 4
        for (int io = 0; io < 32; io++) {
            const int i = ibeg + io;
            const ull xA = dup2(Xp[p][0][0][i]);
            const ull xB = dup2(Xp[p][0][1][i]);
            const ulonglong2 wa = __ldg(reinterpret_cast<const ulonglong2*>(rw1 + i * RHO_H + j0));
            const ulonglong2 wb = __ldg(reinterpret_cast<const ulonglong2*>(rw1 + i * RHO_H + j0 + 4));
            tA[0] = ffma2(xA, wa.x, tA[0]);  tB[0] = ffma2(xB, wa.x, tB[0]);
            tA[1] = ffma2(xA, wa.y, tA[1]);  tB[1] = ffma2(xB, wa.y, tB[1]);
            tA[2] = ffma2(xA, wb.x, tA[2]);  tB[2] = ffma2(xB, wb.x, tB[2]);
            tA[3] = ffma2(xA, wb.y, tA[3]);  tB[3] = ffma2(xB, wb.y, tB[3]);
        }
    }
    // store partials (pre-relu)
    {
        ulonglong2* dA = reinterpret_cast<ulonglong2*>(&ubuf[p][m][0][lane * 4]);
        dA[0] = make_ulonglong2(tA[0], tA[1]);
        dA[1] = make_ulonglong2(tA[2], tA[3]);
        ulonglong2* dB = reinterpret_cast<ulonglong2*>(&ubuf[p][m][1][lane * 4]);
        dB[0] = make_ulonglong2(tB[0], tB[1]);
        dB[1] = make_ulonglong2(tB[2], tB[3]);
    }
    __syncthreads();

    // ---- finish: warp handles its own row (= m). combine partials, relu, rho2 ----
    ull a2 = 0ull;
    {
        const ulonglong2 pa0 = *reinterpret_cast<const ulonglong2*>(&ubuf[p][0][m][lane * 4]);
        const ulonglong2 pa1 = *reinterpret_cast<const ulonglong2*>(&ubuf[p][0][m][lane * 4 + 2]);
        const ulonglong2 pb0 = *reinterpret_cast<const ulonglong2*>(&ubuf[p][1][m][lane * 4]);
        const ulonglong2 pb1v = *reinterpret_cast<const ulonglong2*>(&ubuf[p][1][m][lane * 4 + 2]);
        const ull t0 = add2(pa0.x, pb0.x);
        const ull t1 = add2(pa0.y, pb0.y);
        const ull t2 = add2(pa1.x, pb1v.x);
        const ull t3 = add2(pa1.y, pb1v.y);
        const ulonglong2 q01 = __ldg(reinterpret_cast<const ulonglong2*>(rw2 + 2 * j0));
        const ulonglong2 q23 = __ldg(reinterpret_cast<const ulonglong2*>(rw2 + 2 * j0 + 4));
        const ulonglong2 q45 = __ldg(reinterpret_cast<const ulonglong2*>(rw2 + 2 * j0 + 8));
        const ulonglong2 q67 = __ldg(reinterpret_cast<const ulonglong2*>(rw2 + 2 * j0 + 12));
        const float2 u0 = unpack2(t0), u1 = unpack2(t1);
        const float2 u2 = unpack2(t2), u3 = unpack2(t3);
        a2 = ffma2(dup2(fmaxf(u0.x, 0.f)), q01.x, a2);
        a2 = ffma2(dup2(fmaxf(u0.y, 0.f)), q01.y, a2);
        a2 = ffma2(dup2(fmaxf(u1.x, 0.f)), q23.x, a2);
        a2 = ffma2(dup2(fmaxf(u1.y, 0.f)), q23.y, a2);
        a2 = ffma2(dup2(fmaxf(u2.x, 0.f)), q45.x, a2);
        a2 = ffma2(dup2(fmaxf(u2.y, 0.f)), q45.y, a2);
        a2 = ffma2(dup2(fmaxf(u3.x, 0.f)), q67.x, a2);
        a2 = ffma2(dup2(fmaxf(u3.y, 0.f)), q67.y, a2);
    }

    // ---- barrier term for this warp's row: neighbors n = 2..65, 2 per lane ----
    float bx = 0.f, by = 0.f;
    #pragma unroll
    for (int q = 0; q < 2; q++) {
        const int n = 2 + lane + 32 * q;
        const float px = xs[p][m][4 * n], py = xs[p][m][4 * n + 1];
        const float dm = sqrtf(px * px + py * py) - 0.15f;
        const float inv = 1.f / (dm * dm);
        bx -= px * inv;
        by -= py * inv;
    }

    // ---- warp butterfly reduce (a0, a1, bx, by) ----
    float a0, a1;
    { const float2 u = unpack2(a2); a0 = u.x; a1 = u.y; }
    #pragma unroll
    for (int off = 16; off > 0; off >>= 1) {
        a0 += __shfl_xor_sync(0xffffffff, a0, off);
        a1 += __shfl_xor_sync(0xffffffff, a1, off);
        bx += __shfl_xor_sync(0xffffffff, bx, off);
        by += __shfl_xor_sync(0xffffffff, by, off);
    }

    if (lane == 0) {
        const float r0 = 2.0f * tanhf(a0 + __ldg(rb2))     + bx;
        const float r1 = 2.0f * tanhf(a1 + __ldg(rb2 + 1)) + by;
        out[2 * brow]     = r0;
        out[2 * brow + 1] = r1;
        const unsigned k = max(fkey(r0), fkey(r1));
        atomicMax(&s_max, k);
    }
    __syncthreads();

    // ---- block max -> global; last block applies global rescale ----
    if (tid == 0) {
        atomicMax(&g_maxkey, s_max);
        __threadfence();
        const unsigned prev = atomicAdd(&g_done, 1u);
        s_last = (prev == (unsigned)(gridDim.x - 1));
    }
    __syncthreads();

    if (s_last) {
        __threadfence();
        const float mx    = kinv(atomicAdd(&g_maxkey, 0u));
        const float scale = 2.0f / mx;
        if (scale < 1.0f) {
            float4* o4 = reinterpret_cast<float4*>(out);
            for (int i = tid; i < BATCH * 2 / 4; i += blockDim.x) {
                float4 v = o4[i];
                v.x *= scale; v.y *= scale; v.z *= scale; v.w *= scale;
                o4[i] = v;
            }
        }
        __syncthreads();
        if (tid == 0) {
            g_maxkey = 0u;
            __threadfence();
            atomicExch(&g_done, 0u);
        }
    }
}

extern "C" void kernel_launch(void* const* d_in, const int* in_sizes, int n_in,
                              void* d_out, int out_size)
{
    const float* x   = (const float*)d_in[0];
    const float* pw1 = (const float*)d_in[1];
    const float* pb1 = (const float*)d_in[2];
    const float* pw2 = (const float*)d_in[3];
    const float* pb2 = (const float*)d_in[4];
    const float* rw1 = (const float*)d_in[5];
    const float* rb1 = (const float*)d_in[6];
    const float* rw2 = (const float*)d_in[7];
    const float* rb2 = (const float*)d_in[8];
    float* out = (float*)d_out;

    bn_main_kernel<<<NBLOCKS, 32 * WARPS_PER_BLOCK>>>(
        x, pw1, pb1, pw2, pb2, rw1, rb1, rw2, rb2, out);
}